// round 3
// baseline (speedup 1.0000x reference)
#include <cuda_runtime.h>

#define D 128
#define MAXN 50000
#define MAXE 800000

// -------- scratch (device globals: allocation-free contract) --------
__device__ float g_z[MAXN * D];     // projected features, current layer
__device__ float g_acc[MAXN * D];   // output accumulator (atomic target)
__device__ float g_h[MAXN * D];     // layer output -> next layer input
__device__ float g_el[MAXN];
__device__ float g_er[MAXN];
__device__ int   g_m[MAXN];         // per-dst max (monotone int encoding)
__device__ float g_s[MAXN];         // per-dst sum of exp
__device__ float g_e[MAXE];         // per-edge scratch (e, then ex)

// -------- helpers --------
__device__ __forceinline__ int encf(float f) {
    int i = __float_as_int(f);
    return i >= 0 ? i : (i ^ 0x7fffffff);
}
__device__ __forceinline__ float decf(int i) {
    return __int_as_float(i >= 0 ? i : (i ^ 0x7fffffff));
}
__device__ __forceinline__ unsigned long long pack2(float f) {
    unsigned long long r;
    asm("mov.b64 %0, {%1, %1};" : "=l"(r) : "f"(f));
    return r;
}
__device__ __forceinline__ unsigned long long fma2(unsigned long long a,
                                                   unsigned long long b,
                                                   unsigned long long c) {
    unsigned long long d;
    asm("fma.rn.f32x2 %0, %1, %2, %3;" : "=l"(d) : "l"(a), "l"(b), "l"(c));
    return d;
}
__device__ __forceinline__ void unpack2(unsigned long long v, float& lo, float& hi) {
    asm("mov.b64 {%0, %1}, %2;" : "=f"(lo), "=f"(hi) : "l"(v));
}
__device__ __forceinline__ void red_add_v4(float* p, float4 v) {
    asm volatile("red.global.add.v4.f32 [%0], {%1, %2, %3, %4};"
                 :: "l"(p), "f"(v.x), "f"(v.y), "f"(v.z), "f"(v.w) : "memory");
}

// -------- kernels --------

// zero accumulator + init per-node softmax state
__global__ void k_prep(int n) {
    int i = blockIdx.x * blockDim.x + threadIdx.x;
    if (i < n * D) g_acc[i] = 0.0f;
    if (i < n) { g_m[i] = (int)0x80000000; g_s[i] = 0.0f; }
}

// z = x @ W. Block tile: 64 rows x 128 cols, 256 threads, f32x2 packed FMA.
// Thread (rg = tid/32, c4 = tid%32): 8 rows (4 row-pairs) x 4 cols.
__global__ __launch_bounds__(256) void k_gemm(const float* __restrict__ xin,
                                              const float* __restrict__ W, int n) {
    const float* x = xin ? xin : g_h;
    __shared__ float xt[32][66];    // x chunk, transposed: xt[kk][local_row]
    __shared__ float ws[32][128];   // W chunk: ws[kk][col]
    int tx = threadIdx.x;
    int row0 = blockIdx.x * 64;
    int c4 = tx & 31;
    int rg = tx >> 5;
    unsigned long long acc[4][4];
#pragma unroll
    for (int rp = 0; rp < 4; rp++)
#pragma unroll
        for (int c = 0; c < 4; c++) acc[rp][c] = 0ull;

    for (int k0 = 0; k0 < D; k0 += 32) {
        // load 64x32 x-chunk, transposed into xt
#pragma unroll
        for (int it = 0; it < 2; it++) {
            int t = it * 256 + tx;        // 0..511
            int r = t >> 3, kq = t & 7;
            int grow = row0 + r;
            float4 v = make_float4(0.f, 0.f, 0.f, 0.f);
            if (grow < n) v = *(const float4*)&x[grow * D + k0 + kq * 4];
            xt[kq * 4 + 0][r] = v.x;
            xt[kq * 4 + 1][r] = v.y;
            xt[kq * 4 + 2][r] = v.z;
            xt[kq * 4 + 3][r] = v.w;
        }
        // load 32x128 W-chunk
#pragma unroll
        for (int it = 0; it < 4; it++) {
            int t = it * 256 + tx;        // 0..1023
            int kr = t >> 5, jq = t & 31;
            *(float4*)&ws[kr][jq * 4] = *(const float4*)&W[(k0 + kr) * D + jq * 4];
        }
        __syncthreads();
#pragma unroll
        for (int kk = 0; kk < 32; kk++) {
            float4 wv = *(const float4*)&ws[kk][c4 * 4];
            unsigned long long w2[4];
            w2[0] = pack2(wv.x); w2[1] = pack2(wv.y);
            w2[2] = pack2(wv.z); w2[3] = pack2(wv.w);
#pragma unroll
            for (int rp = 0; rp < 4; rp++) {
                unsigned long long xp =
                    *(const unsigned long long*)&xt[kk][rg * 8 + rp * 2];
                acc[rp][0] = fma2(xp, w2[0], acc[rp][0]);
                acc[rp][1] = fma2(xp, w2[1], acc[rp][1]);
                acc[rp][2] = fma2(xp, w2[2], acc[rp][2]);
                acc[rp][3] = fma2(xp, w2[3], acc[rp][3]);
            }
        }
        __syncthreads();
    }
    // epilogue: unpack row pairs, vector stores
#pragma unroll
    for (int rp = 0; rp < 4; rp++) {
        int r = row0 + rg * 8 + rp * 2;
        float lo[4], hi[4];
#pragma unroll
        for (int c = 0; c < 4; c++) unpack2(acc[rp][c], lo[c], hi[c]);
        if (r < n)
            *(float4*)&g_z[r * D + c4 * 4] = make_float4(lo[0], lo[1], lo[2], lo[3]);
        if (r + 1 < n)
            *(float4*)&g_z[(r + 1) * D + c4 * 4] = make_float4(hi[0], hi[1], hi[2], hi[3]);
    }
}

// el = z . al, er = z . ar  (one warp per node)
__global__ __launch_bounds__(256) void k_dots(const float* __restrict__ al,
                                              const float* __restrict__ ar, int n) {
    int node = (blockIdx.x * blockDim.x + threadIdx.x) >> 5;
    int lane = threadIdx.x & 31;
    if (node >= n) return;
    float4 zv = *(const float4*)&g_z[node * D + lane * 4];
    float4 a = *(const float4*)&al[lane * 4];
    float4 r = *(const float4*)&ar[lane * 4];
    float sl = zv.x * a.x + zv.y * a.y + zv.z * a.z + zv.w * a.w;
    float sr = zv.x * r.x + zv.y * r.y + zv.z * r.z + zv.w * r.w;
#pragma unroll
    for (int o = 16; o > 0; o >>= 1) {
        sl += __shfl_xor_sync(0xffffffffu, sl, o);
        sr += __shfl_xor_sync(0xffffffffu, sr, o);
    }
    if (lane == 0) { g_el[node] = sl; g_er[node] = sr; }
}

// e = leaky_relu(el[src] + er[dst]); segment max over dst
__global__ void k_edgemax(const int* __restrict__ src, const int* __restrict__ dst, int eN) {
    int i = blockIdx.x * blockDim.x + threadIdx.x;
    if (i >= eN) return;
    int s_ = src[i], d_ = dst[i];
    float v = g_el[s_] + g_er[d_];
    v = v > 0.0f ? v : 0.2f * v;
    g_e[i] = v;
    atomicMax(&g_m[d_], encf(v));
}

// ex = exp(e - m[dst]); segment sum over dst
__global__ void k_edgeexp(const int* __restrict__ dst, int eN) {
    int i = blockIdx.x * blockDim.x + threadIdx.x;
    if (i >= eN) return;
    int d_ = dst[i];
    float ex = __expf(g_e[i] - decf(g_m[d_]));
    g_e[i] = ex;
    atomicAdd(&g_s[d_], ex);
}

// acc[dst] += (ex/s[dst]) * z[src]   (one warp per edge, float4 reds)
__global__ __launch_bounds__(256) void k_edgeacc(const int* __restrict__ src,
                                                 const int* __restrict__ dst, int eN) {
    int e = (blockIdx.x * blockDim.x + threadIdx.x) >> 5;
    int lane = threadIdx.x & 31;
    if (e >= eN) return;
    int d_ = dst[e];
    float alpha = 0.f;
    if (lane == 0) alpha = g_e[e] / g_s[d_];
    alpha = __shfl_sync(0xffffffffu, alpha, 0);
    int s_ = src[e];
    float4 zv = *(const float4*)&g_z[s_ * D + lane * 4];
    float4 o = make_float4(zv.x * alpha, zv.y * alpha, zv.z * alpha, zv.w * alpha);
    red_add_v4(&g_acc[d_ * D + lane * 4], o);
}

// h = relu(acc + b)
__global__ void k_fin(const float* __restrict__ b, float* __restrict__ hout, int n) {
    int i = blockIdx.x * blockDim.x + threadIdx.x;
    if (i >= n * D) return;
    float v = g_acc[i] + b[i & (D - 1)];
    v = fmaxf(v, 0.0f);
    float* o = hout ? hout : g_h;
    o[i] = v;
}

// -------- launch --------
extern "C" void kernel_launch(void* const* d_in, const int* in_sizes, int n_in,
                              void* d_out, int out_size) {
    const float* f   = (const float*)d_in[0];
    const int*   src = (const int*)d_in[1];
    const int*   dst = (const int*)d_in[2];
    const float* W[3]  = { (const float*)d_in[3], (const float*)d_in[7],  (const float*)d_in[11] };
    const float* al[3] = { (const float*)d_in[4], (const float*)d_in[8],  (const float*)d_in[12] };
    const float* ar[3] = { (const float*)d_in[5], (const float*)d_in[9],  (const float*)d_in[13] };
    const float* bb[3] = { (const float*)d_in[6], (const float*)d_in[10], (const float*)d_in[14] };

    int n  = in_sizes[0] / D;
    int eN = in_sizes[1];
    float* out = (float*)d_out;

    for (int L = 0; L < 3; L++) {
        const float* xin = (L == 0) ? f : nullptr;    // nullptr -> read g_h
        float* hout = (L == 2) ? out : nullptr;       // nullptr -> write g_h

        k_prep   <<<(n * D + 255) / 256, 256>>>(n);
        k_gemm   <<<(n + 63) / 64, 256>>>(xin, W[L], n);
        k_dots   <<<(n + 7) / 8, 256>>>(al[L], ar[L], n);
        k_edgemax<<<(eN + 255) / 256, 256>>>(src, dst, eN);
        k_edgeexp<<<(eN + 255) / 256, 256>>>(dst, eN);
        k_edgeacc<<<(eN + 7) / 8, 256>>>(src, dst, eN);
        k_fin    <<<(n * D + 255) / 256, 256>>>(bb[L], hout, n);
    }
}

// round 4
// speedup vs baseline: 1.7927x; 1.7927x over previous
#include <cuda_runtime.h>
#include <math_constants.h>

#define D 128
#define MAXN 50000
#define MAXE 800000

// -------- scratch (device globals: allocation-free contract) --------
__device__ float g_z[MAXN * D];       // projected features, current layer
__device__ float g_h[MAXN * D];       // layer output -> next layer input
__device__ float g_el[MAXN];
__device__ float g_er[MAXN];
__device__ float g_e[MAXE];           // per-edge scratch (e, then ex), CSR order
__device__ int   g_cnt[MAXN];         // in-degree histogram
__device__ int   g_off[MAXN + 1];     // CSR offsets by dst
__device__ int   g_woff[MAXN];        // scatter cursors
__device__ int   g_csr_src[MAXE];     // src node per CSR slot

// -------- helpers --------
__device__ __forceinline__ unsigned long long pack2(float f) {
    unsigned long long r;
    asm("mov.b64 %0, {%1, %1};" : "=l"(r) : "f"(f));
    return r;
}
__device__ __forceinline__ unsigned long long fma2(unsigned long long a,
                                                   unsigned long long b,
                                                   unsigned long long c) {
    unsigned long long d;
    asm("fma.rn.f32x2 %0, %1, %2, %3;" : "=l"(d) : "l"(a), "l"(b), "l"(c));
    return d;
}
__device__ __forceinline__ void unpack2(unsigned long long v, float& lo, float& hi) {
    asm("mov.b64 {%0, %1}, %2;" : "=f"(lo), "=f"(hi) : "l"(v));
}

// ================= CSR build (once per launch; graph shared by all layers) ==

__global__ void k_zcnt(int n) {
    int i = blockIdx.x * blockDim.x + threadIdx.x;
    if (i < n) g_cnt[i] = 0;
}

__global__ void k_hist(const int* __restrict__ dst, int eN) {
    int i = blockIdx.x * blockDim.x + threadIdx.x;
    if (i < eN) atomicAdd(&g_cnt[dst[i]], 1);
}

// single-block exclusive scan of g_cnt -> g_off / g_woff
__global__ __launch_bounds__(1024) void k_scan(int n, int eN) {
    __shared__ int part[1024];
    int t = threadIdx.x;
    int chunk = (n + 1023) / 1024;
    int lo = t * chunk;
    int hi = lo + chunk; if (hi > n) hi = n; if (lo > n) lo = n;
    int s = 0;
    for (int i = lo; i < hi; i++) s += g_cnt[i];
    part[t] = s;
    __syncthreads();
    for (int off = 1; off < 1024; off <<= 1) {
        int v = (t >= off) ? part[t - off] : 0;
        __syncthreads();
        part[t] += v;
        __syncthreads();
    }
    int run = (t == 0) ? 0 : part[t - 1];
    for (int i = lo; i < hi; i++) {
        g_off[i] = run; g_woff[i] = run;
        run += g_cnt[i];
    }
    if (t == 0) g_off[n] = eN;
}

__global__ void k_scatter(const int* __restrict__ src, const int* __restrict__ dst, int eN) {
    int i = blockIdx.x * blockDim.x + threadIdx.x;
    if (i >= eN) return;
    int pos = atomicAdd(&g_woff[dst[i]], 1);
    g_csr_src[pos] = src[i];
}

// ================= GEMM (z = x@W) with fused attention dot products =========
// Block tile 64 rows x 128 cols, 256 threads, f32x2 packed FMA.
// Each warp owns 8 full rows -> el/er via in-warp shuffle reduction.
__global__ __launch_bounds__(256) void k_gemm(const float* __restrict__ xin,
                                              const float* __restrict__ W,
                                              const float* __restrict__ al,
                                              const float* __restrict__ ar, int n) {
    const float* x = xin ? xin : g_h;
    __shared__ float xt[32][66];
    __shared__ float ws[32][128];
    int tx = threadIdx.x;
    int row0 = blockIdx.x * 64;
    int c4 = tx & 31;
    int rg = tx >> 5;
    unsigned long long acc[4][4];
#pragma unroll
    for (int rp = 0; rp < 4; rp++)
#pragma unroll
        for (int c = 0; c < 4; c++) acc[rp][c] = 0ull;

    for (int k0 = 0; k0 < D; k0 += 32) {
#pragma unroll
        for (int it = 0; it < 2; it++) {
            int t = it * 256 + tx;
            int r = t >> 3, kq = t & 7;
            int grow = row0 + r;
            float4 v = make_float4(0.f, 0.f, 0.f, 0.f);
            if (grow < n) v = *(const float4*)&x[grow * D + k0 + kq * 4];
            xt[kq * 4 + 0][r] = v.x;
            xt[kq * 4 + 1][r] = v.y;
            xt[kq * 4 + 2][r] = v.z;
            xt[kq * 4 + 3][r] = v.w;
        }
#pragma unroll
        for (int it = 0; it < 4; it++) {
            int t = it * 256 + tx;
            int kr = t >> 5, jq = t & 31;
            *(float4*)&ws[kr][jq * 4] = *(const float4*)&W[(k0 + kr) * D + jq * 4];
        }
        __syncthreads();
#pragma unroll
        for (int kk = 0; kk < 32; kk++) {
            float4 wv = *(const float4*)&ws[kk][c4 * 4];
            unsigned long long w2[4];
            w2[0] = pack2(wv.x); w2[1] = pack2(wv.y);
            w2[2] = pack2(wv.z); w2[3] = pack2(wv.w);
#pragma unroll
            for (int rp = 0; rp < 4; rp++) {
                unsigned long long xp =
                    *(const unsigned long long*)&xt[kk][rg * 8 + rp * 2];
                acc[rp][0] = fma2(xp, w2[0], acc[rp][0]);
                acc[rp][1] = fma2(xp, w2[1], acc[rp][1]);
                acc[rp][2] = fma2(xp, w2[2], acc[rp][2]);
                acc[rp][3] = fma2(xp, w2[3], acc[rp][3]);
            }
        }
        __syncthreads();
    }

    float4 alv = *(const float4*)&al[c4 * 4];
    float4 arv = *(const float4*)&ar[c4 * 4];
#pragma unroll
    for (int rp = 0; rp < 4; rp++) {
        int r = row0 + rg * 8 + rp * 2;
        float lo[4], hi[4];
#pragma unroll
        for (int c = 0; c < 4; c++) unpack2(acc[rp][c], lo[c], hi[c]);
        if (r < n)
            *(float4*)&g_z[r * D + c4 * 4] = make_float4(lo[0], lo[1], lo[2], lo[3]);
        if (r + 1 < n)
            *(float4*)&g_z[(r + 1) * D + c4 * 4] = make_float4(hi[0], hi[1], hi[2], hi[3]);
        // fused attention dots: partial over this lane's 4 cols, then warp reduce
        float el_lo = lo[0]*alv.x + lo[1]*alv.y + lo[2]*alv.z + lo[3]*alv.w;
        float er_lo = lo[0]*arv.x + lo[1]*arv.y + lo[2]*arv.z + lo[3]*arv.w;
        float el_hi = hi[0]*alv.x + hi[1]*alv.y + hi[2]*alv.z + hi[3]*alv.w;
        float er_hi = hi[0]*arv.x + hi[1]*arv.y + hi[2]*arv.z + hi[3]*arv.w;
#pragma unroll
        for (int o = 16; o > 0; o >>= 1) {
            el_lo += __shfl_xor_sync(0xffffffffu, el_lo, o);
            er_lo += __shfl_xor_sync(0xffffffffu, er_lo, o);
            el_hi += __shfl_xor_sync(0xffffffffu, el_hi, o);
            er_hi += __shfl_xor_sync(0xffffffffu, er_hi, o);
        }
        if (c4 == 0) {
            if (r < n)     { g_el[r] = el_lo;     g_er[r] = er_lo; }
            if (r + 1 < n) { g_el[r + 1] = el_hi; g_er[r + 1] = er_hi; }
        }
    }
}

// ===== Fused per-dst softmax + aggregate + bias + ReLU (one warp per dst) ===
__global__ __launch_bounds__(256) void k_edge(const float* __restrict__ b,
                                              float* __restrict__ hout, int n) {
    int d = (blockIdx.x * blockDim.x + threadIdx.x) >> 5;
    int lane = threadIdx.x & 31;
    if (d >= n) return;
    int r0 = g_off[d];
    int deg = g_off[d + 1] - r0;
    float4 acc = make_float4(0.f, 0.f, 0.f, 0.f);

    if (deg > 0) {
        float erd = g_er[d];
        // pass 1: e = leaky_relu(el[src]+er[d]); per-dst max
        float m = -CUDART_INF_F;
        for (int i = lane; i < deg; i += 32) {
            int s = g_csr_src[r0 + i];
            float e = g_el[s] + erd;
            e = e > 0.f ? e : 0.2f * e;
            g_e[r0 + i] = e;
            m = fmaxf(m, e);
        }
#pragma unroll
        for (int o = 16; o > 0; o >>= 1)
            m = fmaxf(m, __shfl_xor_sync(0xffffffffu, m, o));
        // pass 2: exp + sum
        float ssum = 0.f;
        for (int i = lane; i < deg; i += 32) {
            float ex = __expf(g_e[r0 + i] - m);
            g_e[r0 + i] = ex;
            ssum += ex;
        }
#pragma unroll
        for (int o = 16; o > 0; o >>= 1)
            ssum += __shfl_xor_sync(0xffffffffu, ssum, o);
        float inv = 1.0f / ssum;
        // pass 3: acc += alpha * z[src]   (coalesced chunk load + shuffle bcast)
        for (int c = 0; c < deg; c += 32) {
            int idx = c + lane;
            int   sl = 0;
            float exl = 0.f;
            if (idx < deg) { sl = g_csr_src[r0 + idx]; exl = g_e[r0 + idx]; }
            int lim = deg - c; if (lim > 32) lim = 32;
            for (int j = 0; j < lim; j++) {
                int   s = __shfl_sync(0xffffffffu, sl, j);
                float a = __shfl_sync(0xffffffffu, exl, j) * inv;
                float4 zv = *(const float4*)&g_z[s * D + lane * 4];
                acc.x = fmaf(a, zv.x, acc.x);
                acc.y = fmaf(a, zv.y, acc.y);
                acc.z = fmaf(a, zv.z, acc.z);
                acc.w = fmaf(a, zv.w, acc.w);
            }
        }
    }
    float4 bv = *(const float4*)&b[lane * 4];
    float4 o;
    o.x = fmaxf(acc.x + bv.x, 0.f);
    o.y = fmaxf(acc.y + bv.y, 0.f);
    o.z = fmaxf(acc.z + bv.z, 0.f);
    o.w = fmaxf(acc.w + bv.w, 0.f);
    float* out = hout ? hout : g_h;
    *(float4*)&out[d * D + lane * 4] = o;
}

// -------- launch --------
extern "C" void kernel_launch(void* const* d_in, const int* in_sizes, int n_in,
                              void* d_out, int out_size) {
    const float* f   = (const float*)d_in[0];
    const int*   src = (const int*)d_in[1];
    const int*   dst = (const int*)d_in[2];
    const float* W[3]  = { (const float*)d_in[3], (const float*)d_in[7],  (const float*)d_in[11] };
    const float* al[3] = { (const float*)d_in[4], (const float*)d_in[8],  (const float*)d_in[12] };
    const float* ar[3] = { (const float*)d_in[5], (const float*)d_in[9],  (const float*)d_in[13] };
    const float* bb[3] = { (const float*)d_in[6], (const float*)d_in[10], (const float*)d_in[14] };

    int n  = in_sizes[0] / D;
    int eN = in_sizes[1];
    float* out = (float*)d_out;

    // CSR by dst — graph is shared across the 3 layers
    k_zcnt   <<<(n + 255) / 256, 256>>>(n);
    k_hist   <<<(eN + 255) / 256, 256>>>(dst, eN);
    k_scan   <<<1, 1024>>>(n, eN);
    k_scatter<<<(eN + 255) / 256, 256>>>(src, dst, eN);

    for (int L = 0; L < 3; L++) {
        const float* xin = (L == 0) ? f : nullptr;    // nullptr -> read g_h
        float* hout = (L == 2) ? out : nullptr;       // nullptr -> write g_h
        k_gemm<<<(n + 63) / 64, 256>>>(xin, W[L], al[L], ar[L], n);
        k_edge<<<(n + 7) / 8, 256>>>(bb[L], hout, n);
    }
}